// round 14
// baseline (speedup 1.0000x reference)
#include <cuda_runtime.h>
#include <cuda_fp16.h>
#include <cstdint>
#include <math.h>

#define SEQ   4096
#define HID   2048
#define NE    8
#define FFN   1408
#define FFN2  2816
#define CAP   4096

// ---------------- static scratch ----------------
__device__ int   g_count[NE];
__device__ int   g_tok [NE * CAP];
__device__ int   g_slot[NE * CAP];
__device__ float g_twt [SEQ * 2];

__device__ __half g_Xh [(size_t)SEQ * HID];
__device__ __half g_W1h[(size_t)NE * FFN2 * HID];
__device__ __half g_W2h[(size_t)NE * HID * FFN];
__device__ __half g_Ah [(size_t)NE * CAP * FFN];
__device__ __half g_Yh [(size_t)2 * SEQ * HID];

// ---------------- helpers ----------------
__device__ __forceinline__ uint32_t smem_u32(const void* p) {
    uint32_t a;
    asm("{ .reg .u64 t; cvta.to.shared.u64 t, %1; cvt.u32.u64 %0, t; }"
        : "=r"(a) : "l"(p));
    return a;
}
__device__ __forceinline__ void cpa16(uint32_t dst, const void* src) {
    asm volatile("cp.async.cg.shared.global [%0], [%1], 16;" :: "r"(dst), "l"(src));
}
#define CP_COMMIT() asm volatile("cp.async.commit_group;" ::: "memory")
#define CP_WAIT3()  asm volatile("cp.async.wait_group 3;" ::: "memory")
#define CP_WAIT0()  asm volatile("cp.async.wait_group 0;" ::: "memory")

__device__ __forceinline__ void ldsm4(uint32_t& r0, uint32_t& r1, uint32_t& r2,
                                      uint32_t& r3, uint32_t addr) {
    asm volatile("ldmatrix.sync.aligned.m8n8.x4.shared.b16 {%0,%1,%2,%3}, [%4];"
                 : "=r"(r0), "=r"(r1), "=r"(r2), "=r"(r3) : "r"(addr));
}
__device__ __forceinline__ void mma16816(float* c, const uint32_t* a,
                                         uint32_t b0, uint32_t b1) {
    asm volatile(
        "mma.sync.aligned.m16n8k16.row.col.f32.f16.f16.f32 "
        "{%0,%1,%2,%3}, {%4,%5,%6,%7}, {%8,%9}, {%0,%1,%2,%3};"
        : "+f"(c[0]), "+f"(c[1]), "+f"(c[2]), "+f"(c[3])
        : "r"(a[0]), "r"(a[1]), "r"(a[2]), "r"(a[3]), "r"(b0), "r"(b1));
}

// smem tile: 128 rows x 32 k, padded to 40 halves (80B) per row
#define SROW   40
#define TILEB  (128 * SROW * 2)    // 10240 B
#define SBUF   (2 * TILEB)         // (A, B) per stage = 20480 B
#define NSTG   5
#define GSMEM  (NSTG * SBUF)       // 102400 B  (2 CTAs/SM: 204.8 KB)
#define ROWF   132                  // f32 scratch row stride (GEMM1 epilogue)

// ---------------------------------------------------------------------------
__global__ void reset_kernel() {
    if (threadIdx.x < NE) g_count[threadIdx.x] = 0;
}

// ---------------------------------------------------------------------------
#define N4_X  ((size_t)SEQ * HID / 4)
#define N4_W1 ((size_t)NE * FFN2 * HID / 4)
#define N4_W2 ((size_t)NE * HID * FFN / 4)

__global__ void conv_all_kernel(const float4* __restrict__ X,
                                const float4* __restrict__ W1,
                                const float4* __restrict__ W2) {
    size_t total = N4_X + N4_W1 + N4_W2;
    for (size_t i = (size_t)blockIdx.x * blockDim.x + threadIdx.x; i < total;
         i += (size_t)gridDim.x * blockDim.x) {
        const float4* src;
        uint2* dst;
        size_t j;
        if (i < N4_X)              { src = X;  dst = (uint2*)g_Xh;  j = i; }
        else if (i < N4_X + N4_W1) { src = W1; dst = (uint2*)g_W1h; j = i - N4_X; }
        else                       { src = W2; dst = (uint2*)g_W2h; j = i - N4_X - N4_W1; }
        float4 v = src[j];
        __half2 h01 = __floats2half2_rn(v.x, v.y);
        __half2 h23 = __floats2half2_rn(v.z, v.w);
        uint2 u;
        u.x = *(uint32_t*)&h01; u.y = *(uint32_t*)&h23;
        dst[j] = u;
    }
}

// ---------------------------------------------------------------------------
__global__ void router_kernel(const float* __restrict__ X,
                              const float* __restrict__ G,
                              float* __restrict__ out_logits) {
    int warp = (blockIdx.x * blockDim.x + threadIdx.x) >> 5;
    int lane = threadIdx.x & 31;
    if (warp >= SEQ) return;

    const float* x = X + (size_t)warp * HID;
    float acc[NE];
#pragma unroll
    for (int e = 0; e < NE; e++) acc[e] = 0.f;
    for (int h = lane; h < HID; h += 32) {
        float xv = x[h];
        const float* g = G + (size_t)h * NE;
#pragma unroll
        for (int e = 0; e < NE; e++) acc[e] += xv * g[e];
    }
#pragma unroll
    for (int e = 0; e < NE; e++)
#pragma unroll
        for (int o = 16; o > 0; o >>= 1)
            acc[e] += __shfl_xor_sync(0xFFFFFFFFu, acc[e], o);

    if (lane == 0) {
        if (out_logits) {
#pragma unroll
            for (int e = 0; e < NE; e++) out_logits[warp * NE + e] = acc[e];
        }
        float m = acc[0];
#pragma unroll
        for (int e = 1; e < NE; e++) m = fmaxf(m, acc[e]);
        float p[NE];
#pragma unroll
        for (int e = 0; e < NE; e++) p[e] = __expf(acc[e] - m);
        int i1 = 0;
#pragma unroll
        for (int e = 1; e < NE; e++) if (p[e] > p[i1]) i1 = e;
        int i2 = (i1 == 0) ? 1 : 0;
#pragma unroll
        for (int e = 0; e < NE; e++)
            if (e != i1 && p[e] > p[i2]) i2 = e;
        float tot = p[i1] + p[i2];
        g_twt[warp * 2 + 0] = p[i1] / tot;
        g_twt[warp * 2 + 1] = p[i2] / tot;
        int s1 = atomicAdd(&g_count[i1], 1);
        g_tok [i1 * CAP + s1] = warp;
        g_slot[i1 * CAP + s1] = 0;
        int s2 = atomicAdd(&g_count[i2], 1);
        g_tok [i2 * CAP + s2] = warp;
        g_slot[i2 * CAP + s2] = 1;
    }
}

// ---------------------------------------------------------------------------
// Warp/frag mapping (CTA 128x128, 8 warps, warp tile 32x64); B tile at +TILEB
// ---------------------------------------------------------------------------
struct FragAddr { uint32_t aoff, boff; };
__device__ __forceinline__ FragAddr frag_addrs(int tid) {
    int lane = tid & 31, wid = tid >> 5;
    int wm = wid >> 1, wn = wid & 1;
    int t = lane >> 3, l7 = lane & 7;
    FragAddr f;
    f.aoff = (uint32_t)((wm * 32 + (t & 1) * 8 + l7) * (SROW * 2) + (t >> 1) * 16);
    f.boff = (uint32_t)((wn * 64 + (t >> 1) * 8 + l7) * (SROW * 2) + (t & 1) * 16)
             + TILEB;
    return f;
}

__device__ __forceinline__ void compute_kb(uint32_t base, const FragAddr& f,
                                           float acc[2][8][4]) {
#pragma unroll
    for (int k16 = 0; k16 < 2; k16++) {
        uint32_t koff = k16 * 32;
        uint32_t ah[2][4];
        ldsm4(ah[0][0], ah[0][1], ah[0][2], ah[0][3], base + f.aoff + koff);
        ldsm4(ah[1][0], ah[1][1], ah[1][2], ah[1][3], base + f.aoff + koff + 16 * SROW * 2);
        uint32_t bh[4][4];
#pragma unroll
        for (int p = 0; p < 4; p++) {
            uint32_t po = p * 16 * SROW * 2;
            ldsm4(bh[p][0], bh[p][1], bh[p][2], bh[p][3], base + f.boff + po + koff);
        }
#pragma unroll
        for (int mi = 0; mi < 2; mi++)
#pragma unroll
            for (int ni = 0; ni < 8; ni++) {
                int p = ni >> 1, q = (ni & 1) * 2;
                mma16816(acc[mi][ni], ah[mi], bh[p][q], bh[p][q + 1]);
            }
    }
}

// ---------------------------------------------------------------------------
// GEMM1 + fused SiLU*up.  B tile rows 0-63 = gate, 64-127 = up.
// grid (CAP/128, FFN/64, NE).
// ---------------------------------------------------------------------------
#define NKB1 (HID / 32)
__global__ void __launch_bounds__(256, 2) gemm1_kernel() {
    extern __shared__ char smem[];
    int e = blockIdx.z;
    int cnt = g_count[e];
    int row0 = blockIdx.x * 128;
    if (row0 >= cnt) return;
    int col0 = blockIdx.y * 64;

    int tid = threadIdx.x;
    uint32_t sb = smem_u32(smem);

    int lrow = tid >> 1, h = tid & 1;
    int tokA = g_tok[e * CAP + min(row0 + lrow, cnt - 1)];
    const __half* sA = g_Xh + (size_t)tokA * HID + h * 16;
    size_t wr = (lrow < 64) ? ((size_t)e * FFN2 + col0 + lrow)
                            : ((size_t)e * FFN2 + FFN + col0 + (lrow - 64));
    const __half* sB = g_W1h + wr * HID + h * 16;
    uint32_t dsto = (uint32_t)(lrow * (SROW * 2) + h * 32);

#define G1_ISSUE(kb)                                                          \
    do {                                                                      \
        if ((kb) < NKB1) {                                                    \
            uint32_t d = sb + ((kb) % NSTG) * SBUF + dsto;                    \
            int k0 = (kb) * 32;                                               \
            cpa16(d,         sA + k0); cpa16(d + 16,         sA + k0 + 8);    \
            cpa16(d + TILEB, sB + k0); cpa16(d + TILEB + 16, sB + k0 + 8);    \
        }                                                                     \
        CP_COMMIT();                                                          \
    } while (0)

    G1_ISSUE(0);
    G1_ISSUE(1);
    G1_ISSUE(2);
    G1_ISSUE(3);

    FragAddr f = frag_addrs(tid);
    float acc[2][8][4];
#pragma unroll
    for (int mi = 0; mi < 2; mi++)
#pragma unroll
        for (int ni = 0; ni < 8; ni++)
#pragma unroll
            for (int q = 0; q < 4; q++) acc[mi][ni][q] = 0.f;

    // iter kb: committed = 4+kb; wait(<=3 pending) => group kb done ->
    // sync -> issue(kb+4) -> compute(kb). issue targets stage (kb+4)%5 ==
    // (kb-1)%5, whose compute finished before this iteration's sync
    // (WAR-safe), and issuing before compute gives the loads a full
    // compute-phase of extra flight time.
    for (int kb = 0; kb < NKB1; kb++) {
        CP_WAIT3();
        __syncthreads();
        G1_ISSUE(kb + 4);
        compute_kb(sb + (kb % NSTG) * SBUF, f, acc);
    }
#undef G1_ISSUE

    // ---- fused activation epilogue via smem exchange ----
    CP_WAIT0();
    __syncthreads();
    float* sf = (float*)smem;
    {
        int lane = tid & 31, wid = tid >> 5;
        int wm = wid >> 1, wn = wid & 1;
        int gid = lane >> 2, t4 = lane & 3;
#pragma unroll
        for (int mi = 0; mi < 2; mi++) {
            int r = wm * 32 + mi * 16 + gid;
#pragma unroll
            for (int ni = 0; ni < 8; ni++) {
                int c = wn * 64 + ni * 8 + 2 * t4;
                sf[r * ROWF + c]     = acc[mi][ni][0];
                sf[r * ROWF + c + 1] = acc[mi][ni][1];
                sf[(r + 8) * ROWF + c]     = acc[mi][ni][2];
                sf[(r + 8) * ROWF + c + 1] = acc[mi][ni][3];
            }
        }
    }
    __syncthreads();
    {
        int r = tid >> 1, hh = tid & 1;
        int grow = row0 + r;
        if (grow < cnt) {
            uint32_t ph[16];
#pragma unroll
            for (int j = 0; j < 32; j += 2) {
                int c = hh * 32 + j;
                float g0 = sf[r * ROWF + c],      u0 = sf[r * ROWF + 64 + c];
                float g1 = sf[r * ROWF + c + 1],  u1 = sf[r * ROWF + 64 + c + 1];
                float a0 = g0 / (1.f + __expf(-g0)) * u0;
                float a1 = g1 / (1.f + __expf(-g1)) * u1;
                __half2 hv = __floats2half2_rn(a0, a1);
                ph[j >> 1] = *(uint32_t*)&hv;
            }
            size_t base = ((size_t)e * CAP + grow) * FFN + col0 + hh * 32;
            uint4* dh = (uint4*)(g_Ah + base);
#pragma unroll
            for (int q = 0; q < 4; q++)
                dh[q] = make_uint4(ph[4*q], ph[4*q+1], ph[4*q+2], ph[4*q+3]);
        }
    }
}

// ---------------------------------------------------------------------------
// GEMM2: y = act @ W2^T -> per-slot g_Yh (fp16).
// ---------------------------------------------------------------------------
#define NKB2 (FFN / 32)
__global__ void __launch_bounds__(256, 2) gemm2_kernel() {
    extern __shared__ char smem[];
    int e = blockIdx.z;
    int cnt = g_count[e];
    int row0 = blockIdx.x * 128;
    if (row0 >= cnt) return;
    int col0 = blockIdx.y * 128;

    int tid = threadIdx.x;
    uint32_t sb = smem_u32(smem);

    int lrow = tid >> 1, h = tid & 1;
    size_t ar = ((size_t)e * CAP + min(row0 + lrow, cnt - 1)) * FFN;
    const __half* sA = g_Ah + ar + h * 16;
    const __half* sB = g_W2h + ((size_t)e * HID + col0 + lrow) * FFN + h * 16;
    uint32_t dsto = (uint32_t)(lrow * (SROW * 2) + h * 32);

#define G2_ISSUE(kb)                                                          \
    do {                                                                      \
        if ((kb) < NKB2) {                                                    \
            uint32_t d = sb + ((kb) % NSTG) * SBUF + dsto;                    \
            int k0 = (kb) * 32;                                               \
            cpa16(d,         sA + k0); cpa16(d + 16,         sA + k0 + 8);    \
            cpa16(d + TILEB, sB + k0); cpa16(d + TILEB + 16, sB + k0 + 8);    \
        }                                                                     \
        CP_COMMIT();                                                          \
    } while (0)

    G2_ISSUE(0);
    G2_ISSUE(1);
    G2_ISSUE(2);
    G2_ISSUE(3);

    FragAddr f = frag_addrs(tid);
    float acc[2][8][4];
#pragma unroll
    for (int mi = 0; mi < 2; mi++)
#pragma unroll
        for (int ni = 0; ni < 8; ni++)
#pragma unroll
            for (int q = 0; q < 4; q++) acc[mi][ni][q] = 0.f;

    for (int kb = 0; kb < NKB2; kb++) {
        CP_WAIT3();
        __syncthreads();
        G2_ISSUE(kb + 4);
        compute_kb(sb + (kb % NSTG) * SBUF, f, acc);
    }
#undef G2_ISSUE

    int lane = tid & 31, wid = tid >> 5;
    int wm = wid >> 1, wn = wid & 1;
    int gid = lane >> 2, t4 = lane & 3;
#pragma unroll
    for (int mi = 0; mi < 2; mi++) {
        int r0 = row0 + wm * 32 + mi * 16 + gid;
        int r1 = r0 + 8;
        int tok0 = 0, slot0 = 0, tok1 = 0, slot1 = 0;
        if (r0 < cnt) { tok0 = g_tok[e * CAP + r0]; slot0 = g_slot[e * CAP + r0]; }
        if (r1 < cnt) { tok1 = g_tok[e * CAP + r1]; slot1 = g_slot[e * CAP + r1]; }
#pragma unroll
        for (int ni = 0; ni < 8; ni++) {
            int col = col0 + wn * 64 + ni * 8 + 2 * t4;
            if (r0 < cnt) {
                __half2 v = __floats2half2_rn(acc[mi][ni][0], acc[mi][ni][1]);
                *(__half2*)(g_Yh + ((size_t)slot0 * SEQ + tok0) * HID + col) = v;
            }
            if (r1 < cnt) {
                __half2 v = __floats2half2_rn(acc[mi][ni][2], acc[mi][ni][3]);
                *(__half2*)(g_Yh + ((size_t)slot1 * SEQ + tok1) * HID + col) = v;
            }
        }
    }
}

// ---------------------------------------------------------------------------
__global__ void combine_kernel(float4* __restrict__ out) {
    const uint2* y = (const uint2*)g_Yh;
    size_t n = (size_t)SEQ * HID / 4;
    for (size_t i = (size_t)blockIdx.x * blockDim.x + threadIdx.x; i < n;
         i += (size_t)gridDim.x * blockDim.x) {
        int t = (int)(i >> 9);
        float w0 = g_twt[t * 2 + 0];
        float w1 = g_twt[t * 2 + 1];
        uint2 a = y[i];
        uint2 b = y[i + n];
        float2 a01 = __half22float2(*(__half2*)&a.x);
        float2 a23 = __half22float2(*(__half2*)&a.y);
        float2 b01 = __half22float2(*(__half2*)&b.x);
        float2 b23 = __half22float2(*(__half2*)&b.y);
        float4 o;
        o.x = w0 * a01.x + w1 * b01.x;
        o.y = w0 * a01.y + w1 * b01.y;
        o.z = w0 * a23.x + w1 * b23.x;
        o.w = w0 * a23.y + w1 * b23.y;
        out[i] = o;
    }
}

// ---------------------------------------------------------------------------
extern "C" void kernel_launch(void* const* d_in, const int* in_sizes, int n_in,
                              void* d_out, int out_size) {
    const float* X  = (const float*)d_in[0];
    const float* G  = (const float*)d_in[1];
    const float* W1 = (const float*)d_in[2];
    const float* W2 = (const float*)d_in[3];
    float* out = (float*)d_out;

    bool has_logits = (long long)out_size >= (long long)SEQ * HID + (long long)SEQ * NE;
    float* logits = has_logits ? out + (size_t)SEQ * HID : nullptr;

    cudaFuncSetAttribute(gemm1_kernel, cudaFuncAttributeMaxDynamicSharedMemorySize, GSMEM);
    cudaFuncSetAttribute(gemm2_kernel, cudaFuncAttributeMaxDynamicSharedMemorySize, GSMEM);

    reset_kernel<<<1, 32>>>();
    router_kernel<<<SEQ / 8, 256>>>(X, G, logits);
    conv_all_kernel<<<8192, 256>>>((const float4*)X, (const float4*)W1, (const float4*)W2);
    gemm1_kernel<<<dim3(CAP / 128, FFN / 64, NE), 256, GSMEM>>>();
    gemm2_kernel<<<dim3(CAP / 128, HID / 128, NE), 256, GSMEM>>>();
    combine_kernel<<<4096, 256>>>((float4*)out);
}

// round 15
// speedup vs baseline: 1.5303x; 1.5303x over previous
#include <cuda_runtime.h>
#include <cuda_fp16.h>
#include <cstdint>
#include <math.h>

#define SEQ   4096
#define HID   2048
#define NE    8
#define FFN   1408
#define FFN2  2816
#define CAP   4096

// ---------------- static scratch ----------------
__device__ int   g_count[NE];
__device__ int   g_tok [NE * CAP];
__device__ int   g_slot[NE * CAP];
__device__ float g_twt [SEQ * 2];

__device__ __half g_Xh [(size_t)SEQ * HID];
__device__ __half g_W1h[(size_t)NE * FFN2 * HID];
__device__ __half g_W2h[(size_t)NE * HID * FFN];
__device__ __half g_Ah [(size_t)NE * CAP * FFN];
__device__ __half g_Yh [(size_t)2 * SEQ * HID];

// ---------------- helpers ----------------
__device__ __forceinline__ uint32_t smem_u32(const void* p) {
    uint32_t a;
    asm("{ .reg .u64 t; cvta.to.shared.u64 t, %1; cvt.u32.u64 %0, t; }"
        : "=r"(a) : "l"(p));
    return a;
}
__device__ __forceinline__ void cpa16(uint32_t dst, const void* src) {
    asm volatile("cp.async.cg.shared.global [%0], [%1], 16;" :: "r"(dst), "l"(src));
}
#define CP_COMMIT() asm volatile("cp.async.commit_group;" ::: "memory")
#define CP_WAIT2()  asm volatile("cp.async.wait_group 2;" ::: "memory")
#define CP_WAIT0()  asm volatile("cp.async.wait_group 0;" ::: "memory")

__device__ __forceinline__ void ldsm4(uint32_t& r0, uint32_t& r1, uint32_t& r2,
                                      uint32_t& r3, uint32_t addr) {
    asm volatile("ldmatrix.sync.aligned.m8n8.x4.shared.b16 {%0,%1,%2,%3}, [%4];"
                 : "=r"(r0), "=r"(r1), "=r"(r2), "=r"(r3) : "r"(addr));
}
__device__ __forceinline__ void mma16816(float* c, const uint32_t* a,
                                         uint32_t b0, uint32_t b1) {
    asm volatile(
        "mma.sync.aligned.m16n8k16.row.col.f32.f16.f16.f32 "
        "{%0,%1,%2,%3}, {%4,%5,%6,%7}, {%8,%9}, {%0,%1,%2,%3};"
        : "+f"(c[0]), "+f"(c[1]), "+f"(c[2]), "+f"(c[3])
        : "r"(a[0]), "r"(a[1]), "r"(a[2]), "r"(a[3]), "r"(b0), "r"(b1));
}

// smem tile: 128 rows x 32 k, padded to 40 halves (80B) per row
#define SROW   40
#define TILEB  (128 * SROW * 2)    // 10240 B
#define SBUF   (2 * TILEB)         // (A, B) per stage = 20480 B
#define NSTG   4
#define GSMEM  (NSTG * SBUF)       // 81920 B  (2 CTAs/SM)
#define ROWF   132                  // f32 scratch row stride (GEMM1 epilogue)

// ---------------------------------------------------------------------------
__global__ void reset_kernel() {
    if (threadIdx.x < NE) g_count[threadIdx.x] = 0;
}

// ---------------------------------------------------------------------------
#define N4_X  ((size_t)SEQ * HID / 4)
#define N4_W1 ((size_t)NE * FFN2 * HID / 4)
#define N4_W2 ((size_t)NE * HID * FFN / 4)

__global__ void conv_all_kernel(const float4* __restrict__ X,
                                const float4* __restrict__ W1,
                                const float4* __restrict__ W2) {
    size_t total = N4_X + N4_W1 + N4_W2;
    for (size_t i = (size_t)blockIdx.x * blockDim.x + threadIdx.x; i < total;
         i += (size_t)gridDim.x * blockDim.x) {
        const float4* src;
        uint2* dst;
        size_t j;
        if (i < N4_X)              { src = X;  dst = (uint2*)g_Xh;  j = i; }
        else if (i < N4_X + N4_W1) { src = W1; dst = (uint2*)g_W1h; j = i - N4_X; }
        else                       { src = W2; dst = (uint2*)g_W2h; j = i - N4_X - N4_W1; }
        float4 v = src[j];
        __half2 h01 = __floats2half2_rn(v.x, v.y);
        __half2 h23 = __floats2half2_rn(v.z, v.w);
        uint2 u;
        u.x = *(uint32_t*)&h01; u.y = *(uint32_t*)&h23;
        dst[j] = u;
    }
}

// ---------------------------------------------------------------------------
__global__ void router_kernel(const float* __restrict__ X,
                              const float* __restrict__ G,
                              float* __restrict__ out_logits) {
    int warp = (blockIdx.x * blockDim.x + threadIdx.x) >> 5;
    int lane = threadIdx.x & 31;
    if (warp >= SEQ) return;

    const float* x = X + (size_t)warp * HID;
    float acc[NE];
#pragma unroll
    for (int e = 0; e < NE; e++) acc[e] = 0.f;
    for (int h = lane; h < HID; h += 32) {
        float xv = x[h];
        const float* g = G + (size_t)h * NE;
#pragma unroll
        for (int e = 0; e < NE; e++) acc[e] += xv * g[e];
    }
#pragma unroll
    for (int e = 0; e < NE; e++)
#pragma unroll
        for (int o = 16; o > 0; o >>= 1)
            acc[e] += __shfl_xor_sync(0xFFFFFFFFu, acc[e], o);

    if (lane == 0) {
        if (out_logits) {
#pragma unroll
            for (int e = 0; e < NE; e++) out_logits[warp * NE + e] = acc[e];
        }
        float m = acc[0];
#pragma unroll
        for (int e = 1; e < NE; e++) m = fmaxf(m, acc[e]);
        float p[NE];
#pragma unroll
        for (int e = 0; e < NE; e++) p[e] = __expf(acc[e] - m);
        int i1 = 0;
#pragma unroll
        for (int e = 1; e < NE; e++) if (p[e] > p[i1]) i1 = e;
        int i2 = (i1 == 0) ? 1 : 0;
#pragma unroll
        for (int e = 0; e < NE; e++)
            if (e != i1 && p[e] > p[i2]) i2 = e;
        float tot = p[i1] + p[i2];
        g_twt[warp * 2 + 0] = p[i1] / tot;
        g_twt[warp * 2 + 1] = p[i2] / tot;
        int s1 = atomicAdd(&g_count[i1], 1);
        g_tok [i1 * CAP + s1] = warp;
        g_slot[i1 * CAP + s1] = 0;
        int s2 = atomicAdd(&g_count[i2], 1);
        g_tok [i2 * CAP + s2] = warp;
        g_slot[i2 * CAP + s2] = 1;
    }
}

// ---------------------------------------------------------------------------
// Warp/frag mapping (CTA 128x128, 8 warps, warp tile 32x64); B tile at +TILEB
// ---------------------------------------------------------------------------
struct FragAddr { uint32_t aoff, boff; };
__device__ __forceinline__ FragAddr frag_addrs(int tid) {
    int lane = tid & 31, wid = tid >> 5;
    int wm = wid >> 1, wn = wid & 1;
    int t = lane >> 3, l7 = lane & 7;
    FragAddr f;
    f.aoff = (uint32_t)((wm * 32 + (t & 1) * 8 + l7) * (SROW * 2) + (t >> 1) * 16);
    f.boff = (uint32_t)((wn * 64 + (t >> 1) * 8 + l7) * (SROW * 2) + (t & 1) * 16)
             + TILEB;
    return f;
}

__device__ __forceinline__ void compute_kb(uint32_t base, const FragAddr& f,
                                           float acc[2][8][4]) {
#pragma unroll
    for (int k16 = 0; k16 < 2; k16++) {
        uint32_t koff = k16 * 32;
        uint32_t ah[2][4];
        ldsm4(ah[0][0], ah[0][1], ah[0][2], ah[0][3], base + f.aoff + koff);
        ldsm4(ah[1][0], ah[1][1], ah[1][2], ah[1][3], base + f.aoff + koff + 16 * SROW * 2);
        uint32_t bh[4][4];
#pragma unroll
        for (int p = 0; p < 4; p++) {
            uint32_t po = p * 16 * SROW * 2;
            ldsm4(bh[p][0], bh[p][1], bh[p][2], bh[p][3], base + f.boff + po + koff);
        }
#pragma unroll
        for (int mi = 0; mi < 2; mi++)
#pragma unroll
            for (int ni = 0; ni < 8; ni++) {
                int p = ni >> 1, q = (ni & 1) * 2;
                mma16816(acc[mi][ni], ah[mi], bh[p][q], bh[p][q + 1]);
            }
    }
}

// ---------------------------------------------------------------------------
// GEMM1 + fused SiLU*up.  B tile rows 0-63 = gate, 64-127 = up.
// grid (CAP/128, FFN/64, NE).
// ---------------------------------------------------------------------------
#define NKB1 (HID / 32)
__global__ void __launch_bounds__(256, 2) gemm1_kernel() {
    extern __shared__ char smem[];
    int e = blockIdx.z;
    int cnt = g_count[e];
    int row0 = blockIdx.x * 128;
    if (row0 >= cnt) return;
    int col0 = blockIdx.y * 64;

    int tid = threadIdx.x;
    uint32_t sb = smem_u32(smem);

    int lrow = tid >> 1, h = tid & 1;
    int tokA = g_tok[e * CAP + min(row0 + lrow, cnt - 1)];
    const __half* sA = g_Xh + (size_t)tokA * HID + h * 16;
    size_t wr = (lrow < 64) ? ((size_t)e * FFN2 + col0 + lrow)
                            : ((size_t)e * FFN2 + FFN + col0 + (lrow - 64));
    const __half* sB = g_W1h + wr * HID + h * 16;
    uint32_t dsto = (uint32_t)(lrow * (SROW * 2) + h * 32);

#define G1_ISSUE(kb)                                                          \
    do {                                                                      \
        if ((kb) < NKB1) {                                                    \
            uint32_t d = sb + ((kb) % NSTG) * SBUF + dsto;                    \
            int k0 = (kb) * 32;                                               \
            cpa16(d,         sA + k0); cpa16(d + 16,         sA + k0 + 8);    \
            cpa16(d + TILEB, sB + k0); cpa16(d + TILEB + 16, sB + k0 + 8);    \
        }                                                                     \
        CP_COMMIT();                                                          \
    } while (0)

    G1_ISSUE(0);
    G1_ISSUE(1);
    G1_ISSUE(2);

    FragAddr f = frag_addrs(tid);
    float acc[2][8][4];
#pragma unroll
    for (int mi = 0; mi < 2; mi++)
#pragma unroll
        for (int ni = 0; ni < 8; ni++)
#pragma unroll
            for (int q = 0; q < 4; q++) acc[mi][ni][q] = 0.f;

    // iter kb: committed = 3+kb; wait(<=2 pending) => group kb done ->
    // sync -> issue(kb+3) -> compute(kb). issue targets stage (kb+3)%4 ==
    // (kb-1)%4, computed last iteration (done before this sync) => WAR-safe.
    // Issuing before compute gives the loads one extra compute-phase of
    // flight time at zero register/ALU cost (stage modulo stays power-of-2).
    for (int kb = 0; kb < NKB1; kb++) {
        CP_WAIT2();
        __syncthreads();
        G1_ISSUE(kb + 3);
        compute_kb(sb + (kb % NSTG) * SBUF, f, acc);
    }
#undef G1_ISSUE

    // ---- fused activation epilogue via smem exchange ----
    CP_WAIT0();
    __syncthreads();
    float* sf = (float*)smem;
    {
        int lane = tid & 31, wid = tid >> 5;
        int wm = wid >> 1, wn = wid & 1;
        int gid = lane >> 2, t4 = lane & 3;
#pragma unroll
        for (int mi = 0; mi < 2; mi++) {
            int r = wm * 32 + mi * 16 + gid;
#pragma unroll
            for (int ni = 0; ni < 8; ni++) {
                int c = wn * 64 + ni * 8 + 2 * t4;
                sf[r * ROWF + c]     = acc[mi][ni][0];
                sf[r * ROWF + c + 1] = acc[mi][ni][1];
                sf[(r + 8) * ROWF + c]     = acc[mi][ni][2];
                sf[(r + 8) * ROWF + c + 1] = acc[mi][ni][3];
            }
        }
    }
    __syncthreads();
    {
        int r = tid >> 1, hh = tid & 1;
        int grow = row0 + r;
        if (grow < cnt) {
            uint32_t ph[16];
#pragma unroll
            for (int j = 0; j < 32; j += 2) {
                int c = hh * 32 + j;
                float g0 = sf[r * ROWF + c],      u0 = sf[r * ROWF + 64 + c];
                float g1 = sf[r * ROWF + c + 1],  u1 = sf[r * ROWF + 64 + c + 1];
                float a0 = g0 / (1.f + __expf(-g0)) * u0;
                float a1 = g1 / (1.f + __expf(-g1)) * u1;
                __half2 hv = __floats2half2_rn(a0, a1);
                ph[j >> 1] = *(uint32_t*)&hv;
            }
            size_t base = ((size_t)e * CAP + grow) * FFN + col0 + hh * 32;
            uint4* dh = (uint4*)(g_Ah + base);
#pragma unroll
            for (int q = 0; q < 4; q++)
                dh[q] = make_uint4(ph[4*q], ph[4*q+1], ph[4*q+2], ph[4*q+3]);
        }
    }
}

// ---------------------------------------------------------------------------
// GEMM2: y = act @ W2^T -> per-slot g_Yh (fp16).
// ---------------------------------------------------------------------------
#define NKB2 (FFN / 32)
__global__ void __launch_bounds__(256, 2) gemm2_kernel() {
    extern __shared__ char smem[];
    int e = blockIdx.z;
    int cnt = g_count[e];
    int row0 = blockIdx.x * 128;
    if (row0 >= cnt) return;
    int col0 = blockIdx.y * 128;

    int tid = threadIdx.x;
    uint32_t sb = smem_u32(smem);

    int lrow = tid >> 1, h = tid & 1;
    size_t ar = ((size_t)e * CAP + min(row0 + lrow, cnt - 1)) * FFN;
    const __half* sA = g_Ah + ar + h * 16;
    const __half* sB = g_W2h + ((size_t)e * HID + col0 + lrow) * FFN + h * 16;
    uint32_t dsto = (uint32_t)(lrow * (SROW * 2) + h * 32);

#define G2_ISSUE(kb)                                                          \
    do {                                                                      \
        if ((kb) < NKB2) {                                                    \
            uint32_t d = sb + ((kb) % NSTG) * SBUF + dsto;                    \
            int k0 = (kb) * 32;                                               \
            cpa16(d,         sA + k0); cpa16(d + 16,         sA + k0 + 8);    \
            cpa16(d + TILEB, sB + k0); cpa16(d + TILEB + 16, sB + k0 + 8);    \
        }                                                                     \
        CP_COMMIT();                                                          \
    } while (0)

    G2_ISSUE(0);
    G2_ISSUE(1);
    G2_ISSUE(2);

    FragAddr f = frag_addrs(tid);
    float acc[2][8][4];
#pragma unroll
    for (int mi = 0; mi < 2; mi++)
#pragma unroll
        for (int ni = 0; ni < 8; ni++)
#pragma unroll
            for (int q = 0; q < 4; q++) acc[mi][ni][q] = 0.f;

    for (int kb = 0; kb < NKB2; kb++) {
        CP_WAIT2();
        __syncthreads();
        G2_ISSUE(kb + 3);
        compute_kb(sb + (kb % NSTG) * SBUF, f, acc);
    }
#undef G2_ISSUE

    int lane = tid & 31, wid = tid >> 5;
    int wm = wid >> 1, wn = wid & 1;
    int gid = lane >> 2, t4 = lane & 3;
#pragma unroll
    for (int mi = 0; mi < 2; mi++) {
        int r0 = row0 + wm * 32 + mi * 16 + gid;
        int r1 = r0 + 8;
        int tok0 = 0, slot0 = 0, tok1 = 0, slot1 = 0;
        if (r0 < cnt) { tok0 = g_tok[e * CAP + r0]; slot0 = g_slot[e * CAP + r0]; }
        if (r1 < cnt) { tok1 = g_tok[e * CAP + r1]; slot1 = g_slot[e * CAP + r1]; }
#pragma unroll
        for (int ni = 0; ni < 8; ni++) {
            int col = col0 + wn * 64 + ni * 8 + 2 * t4;
            if (r0 < cnt) {
                __half2 v = __floats2half2_rn(acc[mi][ni][0], acc[mi][ni][1]);
                *(__half2*)(g_Yh + ((size_t)slot0 * SEQ + tok0) * HID + col) = v;
            }
            if (r1 < cnt) {
                __half2 v = __floats2half2_rn(acc[mi][ni][2], acc[mi][ni][3]);
                *(__half2*)(g_Yh + ((size_t)slot1 * SEQ + tok1) * HID + col) = v;
            }
        }
    }
}

// ---------------------------------------------------------------------------
__global__ void combine_kernel(float4* __restrict__ out) {
    const uint2* y = (const uint2*)g_Yh;
    size_t n = (size_t)SEQ * HID / 4;
    for (size_t i = (size_t)blockIdx.x * blockDim.x + threadIdx.x; i < n;
         i += (size_t)gridDim.x * blockDim.x) {
        int t = (int)(i >> 9);
        float w0 = g_twt[t * 2 + 0];
        float w1 = g_twt[t * 2 + 1];
        uint2 a = y[i];
        uint2 b = y[i + n];
        float2 a01 = __half22float2(*(__half2*)&a.x);
        float2 a23 = __half22float2(*(__half2*)&a.y);
        float2 b01 = __half22float2(*(__half2*)&b.x);
        float2 b23 = __half22float2(*(__half2*)&b.y);
        float4 o;
        o.x = w0 * a01.x + w1 * b01.x;
        o.y = w0 * a01.y + w1 * b01.y;
        o.z = w0 * a23.x + w1 * b23.x;
        o.w = w0 * a23.y + w1 * b23.y;
        out[i] = o;
    }
}

// ---------------------------------------------------------------------------
extern "C" void kernel_launch(void* const* d_in, const int* in_sizes, int n_in,
                              void* d_out, int out_size) {
    const float* X  = (const float*)d_in[0];
    const float* G  = (const float*)d_in[1];
    const float* W1 = (const float*)d_in[2];
    const float* W2 = (const float*)d_in[3];
    float* out = (float*)d_out;

    bool has_logits = (long long)out_size >= (long long)SEQ * HID + (long long)SEQ * NE;
    float* logits = has_logits ? out + (size_t)SEQ * HID : nullptr;

    cudaFuncSetAttribute(gemm1_kernel, cudaFuncAttributeMaxDynamicSharedMemorySize, GSMEM);
    cudaFuncSetAttribute(gemm2_kernel, cudaFuncAttributeMaxDynamicSharedMemorySize, GSMEM);

    reset_kernel<<<1, 32>>>();
    router_kernel<<<SEQ / 8, 256>>>(X, G, logits);
    conv_all_kernel<<<8192, 256>>>((const float4*)X, (const float4*)W1, (const float4*)W2);
    gemm1_kernel<<<dim3(CAP / 128, FFN / 64, NE), 256, GSMEM>>>();
    gemm2_kernel<<<dim3(CAP / 128, HID / 128, NE), 256, GSMEM>>>();
    combine_kernel<<<4096, 256>>>((float4*)out);
}

// round 16
// speedup vs baseline: 1.6606x; 1.0851x over previous
#include <cuda_runtime.h>
#include <cuda_fp16.h>
#include <cstdint>
#include <math.h>

#define SEQ   4096
#define HID   2048
#define NE    8
#define FFN   1408
#define FFN2  2816
#define CAP   4096

// ---------------- static scratch ----------------
__device__ int   g_count[NE];
__device__ int   g_tok [NE * CAP];
__device__ int   g_slot[NE * CAP];
__device__ float g_twt [SEQ * 2];

__device__ __half g_Xh [(size_t)SEQ * HID];
__device__ __half g_W1h[(size_t)NE * FFN2 * HID];
__device__ __half g_W2h[(size_t)NE * HID * FFN];
__device__ __half g_Ah [(size_t)NE * CAP * FFN];
__device__ __half g_Yh [(size_t)2 * SEQ * HID];

// ---------------- helpers ----------------
__device__ __forceinline__ uint32_t smem_u32(const void* p) {
    uint32_t a;
    asm("{ .reg .u64 t; cvta.to.shared.u64 t, %1; cvt.u32.u64 %0, t; }"
        : "=r"(a) : "l"(p));
    return a;
}
__device__ __forceinline__ void cpa16(uint32_t dst, const void* src) {
    asm volatile("cp.async.cg.shared.global [%0], [%1], 16;" :: "r"(dst), "l"(src));
}
#define CP_COMMIT() asm volatile("cp.async.commit_group;" ::: "memory")
#define CP_WAIT2()  asm volatile("cp.async.wait_group 2;" ::: "memory")
#define CP_WAIT0()  asm volatile("cp.async.wait_group 0;" ::: "memory")

__device__ __forceinline__ void ldsm4(uint32_t& r0, uint32_t& r1, uint32_t& r2,
                                      uint32_t& r3, uint32_t addr) {
    asm volatile("ldmatrix.sync.aligned.m8n8.x4.shared.b16 {%0,%1,%2,%3}, [%4];"
                 : "=r"(r0), "=r"(r1), "=r"(r2), "=r"(r3) : "r"(addr));
}
__device__ __forceinline__ void mma16816(float* c, const uint32_t* a,
                                         uint32_t b0, uint32_t b1) {
    asm volatile(
        "mma.sync.aligned.m16n8k16.row.col.f32.f16.f16.f32 "
        "{%0,%1,%2,%3}, {%4,%5,%6,%7}, {%8,%9}, {%0,%1,%2,%3};"
        : "+f"(c[0]), "+f"(c[1]), "+f"(c[2]), "+f"(c[3])
        : "r"(a[0]), "r"(a[1]), "r"(a[2]), "r"(a[3]), "r"(b0), "r"(b1));
}

// smem tile: 128 rows x 32 k, padded to 40 halves (80B) per row
#define SROW   40
#define TILEB  (128 * SROW * 2)    // 10240 B
#define SBUF   (2 * TILEB)         // (A, B) per stage = 20480 B
#define NSTG   4
#define GSMEM  (NSTG * SBUF)       // 81920 B  (2 CTAs/SM)
#define ROWF   132                  // f32 scratch row stride (GEMM1 epilogue)

// ---------------------------------------------------------------------------
__global__ void reset_kernel() {
    if (threadIdx.x < NE) g_count[threadIdx.x] = 0;
}

// ---------------------------------------------------------------------------
#define N4_X  ((size_t)SEQ * HID / 4)
#define N4_W1 ((size_t)NE * FFN2 * HID / 4)
#define N4_W2 ((size_t)NE * HID * FFN / 4)

__global__ void conv_all_kernel(const float4* __restrict__ X,
                                const float4* __restrict__ W1,
                                const float4* __restrict__ W2) {
    size_t total = N4_X + N4_W1 + N4_W2;
    for (size_t i = (size_t)blockIdx.x * blockDim.x + threadIdx.x; i < total;
         i += (size_t)gridDim.x * blockDim.x) {
        const float4* src;
        uint2* dst;
        size_t j;
        if (i < N4_X)              { src = X;  dst = (uint2*)g_Xh;  j = i; }
        else if (i < N4_X + N4_W1) { src = W1; dst = (uint2*)g_W1h; j = i - N4_X; }
        else                       { src = W2; dst = (uint2*)g_W2h; j = i - N4_X - N4_W1; }
        float4 v = src[j];
        __half2 h01 = __floats2half2_rn(v.x, v.y);
        __half2 h23 = __floats2half2_rn(v.z, v.w);
        uint2 u;
        u.x = *(uint32_t*)&h01; u.y = *(uint32_t*)&h23;
        dst[j] = u;
    }
}

// ---------------------------------------------------------------------------
__global__ void router_kernel(const float* __restrict__ X,
                              const float* __restrict__ G,
                              float* __restrict__ out_logits) {
    int warp = (blockIdx.x * blockDim.x + threadIdx.x) >> 5;
    int lane = threadIdx.x & 31;
    if (warp >= SEQ) return;

    const float* x = X + (size_t)warp * HID;
    float acc[NE];
#pragma unroll
    for (int e = 0; e < NE; e++) acc[e] = 0.f;
    for (int h = lane; h < HID; h += 32) {
        float xv = x[h];
        const float* g = G + (size_t)h * NE;
#pragma unroll
        for (int e = 0; e < NE; e++) acc[e] += xv * g[e];
    }
#pragma unroll
    for (int e = 0; e < NE; e++)
#pragma unroll
        for (int o = 16; o > 0; o >>= 1)
            acc[e] += __shfl_xor_sync(0xFFFFFFFFu, acc[e], o);

    if (lane == 0) {
        if (out_logits) {
#pragma unroll
            for (int e = 0; e < NE; e++) out_logits[warp * NE + e] = acc[e];
        }
        float m = acc[0];
#pragma unroll
        for (int e = 1; e < NE; e++) m = fmaxf(m, acc[e]);
        float p[NE];
#pragma unroll
        for (int e = 0; e < NE; e++) p[e] = __expf(acc[e] - m);
        int i1 = 0;
#pragma unroll
        for (int e = 1; e < NE; e++) if (p[e] > p[i1]) i1 = e;
        int i2 = (i1 == 0) ? 1 : 0;
#pragma unroll
        for (int e = 0; e < NE; e++)
            if (e != i1 && p[e] > p[i2]) i2 = e;
        float tot = p[i1] + p[i2];
        g_twt[warp * 2 + 0] = p[i1] / tot;
        g_twt[warp * 2 + 1] = p[i2] / tot;
        int s1 = atomicAdd(&g_count[i1], 1);
        g_tok [i1 * CAP + s1] = warp;
        g_slot[i1 * CAP + s1] = 0;
        int s2 = atomicAdd(&g_count[i2], 1);
        g_tok [i2 * CAP + s2] = warp;
        g_slot[i2 * CAP + s2] = 1;
    }
}

// ---------------------------------------------------------------------------
// CTA 128x128, 16 warps (4 wm x 4 wn), warp tile 32x32; B tile at +TILEB
// ---------------------------------------------------------------------------
struct FragAddr { uint32_t aoff, boff; };
__device__ __forceinline__ FragAddr frag_addrs(int tid) {
    int lane = tid & 31, wid = tid >> 5;
    int wm = wid >> 2, wn = wid & 3;
    int t = lane >> 3, l7 = lane & 7;
    FragAddr f;
    f.aoff = (uint32_t)((wm * 32 + (t & 1) * 8 + l7) * (SROW * 2) + (t >> 1) * 16);
    f.boff = (uint32_t)((wn * 32 + (t >> 1) * 8 + l7) * (SROW * 2) + (t & 1) * 16)
             + TILEB;
    return f;
}

__device__ __forceinline__ void compute_kb(uint32_t base, const FragAddr& f,
                                           float acc[2][4][4]) {
#pragma unroll
    for (int k16 = 0; k16 < 2; k16++) {
        uint32_t koff = k16 * 32;
        uint32_t ah[2][4];
        ldsm4(ah[0][0], ah[0][1], ah[0][2], ah[0][3], base + f.aoff + koff);
        ldsm4(ah[1][0], ah[1][1], ah[1][2], ah[1][3], base + f.aoff + koff + 16 * SROW * 2);
        uint32_t bh[2][4];
#pragma unroll
        for (int p = 0; p < 2; p++) {
            uint32_t po = p * 16 * SROW * 2;
            ldsm4(bh[p][0], bh[p][1], bh[p][2], bh[p][3], base + f.boff + po + koff);
        }
#pragma unroll
        for (int mi = 0; mi < 2; mi++)
#pragma unroll
            for (int ni = 0; ni < 4; ni++) {
                int p = ni >> 1, q = (ni & 1) * 2;
                mma16816(acc[mi][ni], ah[mi], bh[p][q], bh[p][q + 1]);
            }
    }
}

// ---------------------------------------------------------------------------
// GEMM1 + fused SiLU*up.  B tile rows 0-63 = gate, 64-127 = up.
// grid (CAP/128, FFN/64, NE), 512 threads.
// ---------------------------------------------------------------------------
#define NKB1 (HID / 32)
__global__ void __launch_bounds__(512, 2) gemm1_kernel() {
    extern __shared__ char smem[];
    int e = blockIdx.z;
    int cnt = g_count[e];
    int row0 = blockIdx.x * 128;
    if (row0 >= cnt) return;
    int col0 = blockIdx.y * 64;

    int tid = threadIdx.x;
    uint32_t sb = smem_u32(smem);

    // loaders: 512 threads; each does one 16B A chunk + one 16B B chunk
    int lrow = tid >> 2, q4 = tid & 3;     // row 0..127, 16B quarter 0..3
    int tokA = g_tok[e * CAP + min(row0 + lrow, cnt - 1)];
    const __half* sA = g_Xh + (size_t)tokA * HID + q4 * 8;
    size_t wr = (lrow < 64) ? ((size_t)e * FFN2 + col0 + lrow)
                            : ((size_t)e * FFN2 + FFN + col0 + (lrow - 64));
    const __half* sB = g_W1h + wr * HID + q4 * 8;
    uint32_t dstA = (uint32_t)(lrow * (SROW * 2) + q4 * 16);
    uint32_t dstB = dstA + TILEB;

#define G1_ISSUE(kb)                                                          \
    do {                                                                      \
        if ((kb) < NKB1) {                                                    \
            uint32_t st = sb + ((kb) % NSTG) * SBUF;                          \
            int k0 = (kb) * 32;                                               \
            cpa16(st + dstA, sA + k0);                                        \
            cpa16(st + dstB, sB + k0);                                        \
        }                                                                     \
        CP_COMMIT();                                                          \
    } while (0)

    G1_ISSUE(0);
    G1_ISSUE(1);
    G1_ISSUE(2);

    FragAddr f = frag_addrs(tid);
    float acc[2][4][4];
#pragma unroll
    for (int mi = 0; mi < 2; mi++)
#pragma unroll
        for (int ni = 0; ni < 4; ni++)
#pragma unroll
            for (int qq = 0; qq < 4; qq++) acc[mi][ni][qq] = 0.f;

    // iter kb: committed = 3+kb; wait(<=2 pending) => group kb done ->
    // sync -> compute(kb) -> issue(kb+3) into stage (kb-1)%4 (WAR-safe).
    for (int kb = 0; kb < NKB1; kb++) {
        CP_WAIT2();
        __syncthreads();
        compute_kb(sb + (kb % NSTG) * SBUF, f, acc);
        G1_ISSUE(kb + 3);
    }
#undef G1_ISSUE

    // ---- fused activation epilogue via smem exchange ----
    CP_WAIT0();
    __syncthreads();
    float* sf = (float*)smem;
    {
        int lane = tid & 31, wid = tid >> 5;
        int wm = wid >> 2, wn = wid & 3;
        int gid = lane >> 2, t4 = lane & 3;
#pragma unroll
        for (int mi = 0; mi < 2; mi++) {
            int r = wm * 32 + mi * 16 + gid;
#pragma unroll
            for (int ni = 0; ni < 4; ni++) {
                int c = wn * 32 + ni * 8 + 2 * t4;
                sf[r * ROWF + c]     = acc[mi][ni][0];
                sf[r * ROWF + c + 1] = acc[mi][ni][1];
                sf[(r + 8) * ROWF + c]     = acc[mi][ni][2];
                sf[(r + 8) * ROWF + c + 1] = acc[mi][ni][3];
            }
        }
    }
    __syncthreads();
    {
        int r = tid >> 2, seg = tid & 3;   // 128 rows, 4 threads/row, 16 cols each
        int grow = row0 + r;
        if (grow < cnt) {
            uint32_t ph[8];
#pragma unroll
            for (int j = 0; j < 16; j += 2) {
                int c = seg * 16 + j;
                float g0 = sf[r * ROWF + c],      u0 = sf[r * ROWF + 64 + c];
                float g1 = sf[r * ROWF + c + 1],  u1 = sf[r * ROWF + 64 + c + 1];
                float a0 = g0 / (1.f + __expf(-g0)) * u0;
                float a1 = g1 / (1.f + __expf(-g1)) * u1;
                __half2 hv = __floats2half2_rn(a0, a1);
                ph[j >> 1] = *(uint32_t*)&hv;
            }
            size_t base = ((size_t)e * CAP + grow) * FFN + col0 + seg * 16;
            uint4* dh = (uint4*)(g_Ah + base);
            dh[0] = make_uint4(ph[0], ph[1], ph[2], ph[3]);
            dh[1] = make_uint4(ph[4], ph[5], ph[6], ph[7]);
        }
    }
}

// ---------------------------------------------------------------------------
// GEMM2: y = act @ W2^T -> per-slot g_Yh (fp16). grid (CAP/128, HID/128, NE).
// ---------------------------------------------------------------------------
#define NKB2 (FFN / 32)
__global__ void __launch_bounds__(512, 2) gemm2_kernel() {
    extern __shared__ char smem[];
    int e = blockIdx.z;
    int cnt = g_count[e];
    int row0 = blockIdx.x * 128;
    if (row0 >= cnt) return;
    int col0 = blockIdx.y * 128;

    int tid = threadIdx.x;
    uint32_t sb = smem_u32(smem);

    int lrow = tid >> 2, q4 = tid & 3;
    size_t ar = ((size_t)e * CAP + min(row0 + lrow, cnt - 1)) * FFN;
    const __half* sA = g_Ah + ar + q4 * 8;
    const __half* sB = g_W2h + ((size_t)e * HID + col0 + lrow) * FFN + q4 * 8;
    uint32_t dstA = (uint32_t)(lrow * (SROW * 2) + q4 * 16);
    uint32_t dstB = dstA + TILEB;

#define G2_ISSUE(kb)                                                          \
    do {                                                                      \
        if ((kb) < NKB2) {                                                    \
            uint32_t st = sb + ((kb) % NSTG) * SBUF;                          \
            int k0 = (kb) * 32;                                               \
            cpa16(st + dstA, sA + k0);                                        \
            cpa16(st + dstB, sB + k0);                                        \
        }                                                                     \
        CP_COMMIT();                                                          \
    } while (0)

    G2_ISSUE(0);
    G2_ISSUE(1);
    G2_ISSUE(2);

    FragAddr f = frag_addrs(tid);
    float acc[2][4][4];
#pragma unroll
    for (int mi = 0; mi < 2; mi++)
#pragma unroll
        for (int ni = 0; ni < 4; ni++)
#pragma unroll
            for (int qq = 0; qq < 4; qq++) acc[mi][ni][qq] = 0.f;

    for (int kb = 0; kb < NKB2; kb++) {
        CP_WAIT2();
        __syncthreads();
        compute_kb(sb + (kb % NSTG) * SBUF, f, acc);
        G2_ISSUE(kb + 3);
    }
#undef G2_ISSUE

    int lane = tid & 31, wid = tid >> 5;
    int wm = wid >> 2, wn = wid & 3;
    int gid = lane >> 2, t4 = lane & 3;
#pragma unroll
    for (int mi = 0; mi < 2; mi++) {
        int r0 = row0 + wm * 32 + mi * 16 + gid;
        int r1 = r0 + 8;
        int tok0 = 0, slot0 = 0, tok1 = 0, slot1 = 0;
        if (r0 < cnt) { tok0 = g_tok[e * CAP + r0]; slot0 = g_slot[e * CAP + r0]; }
        if (r1 < cnt) { tok1 = g_tok[e * CAP + r1]; slot1 = g_slot[e * CAP + r1]; }
#pragma unroll
        for (int ni = 0; ni < 4; ni++) {
            int col = col0 + wn * 32 + ni * 8 + 2 * t4;
            if (r0 < cnt) {
                __half2 v = __floats2half2_rn(acc[mi][ni][0], acc[mi][ni][1]);
                *(__half2*)(g_Yh + ((size_t)slot0 * SEQ + tok0) * HID + col) = v;
            }
            if (r1 < cnt) {
                __half2 v = __floats2half2_rn(acc[mi][ni][2], acc[mi][ni][3]);
                *(__half2*)(g_Yh + ((size_t)slot1 * SEQ + tok1) * HID + col) = v;
            }
        }
    }
}

// ---------------------------------------------------------------------------
__global__ void combine_kernel(float4* __restrict__ out) {
    const uint2* y = (const uint2*)g_Yh;
    size_t n = (size_t)SEQ * HID / 4;
    for (size_t i = (size_t)blockIdx.x * blockDim.x + threadIdx.x; i < n;
         i += (size_t)gridDim.x * blockDim.x) {
        int t = (int)(i >> 9);
        float w0 = g_twt[t * 2 + 0];
        float w1 = g_twt[t * 2 + 1];
        uint2 a = y[i];
        uint2 b = y[i + n];
        float2 a01 = __half22float2(*(__half2*)&a.x);
        float2 a23 = __half22float2(*(__half2*)&a.y);
        float2 b01 = __half22float2(*(__half2*)&b.x);
        float2 b23 = __half22float2(*(__half2*)&b.y);
        float4 o;
        o.x = w0 * a01.x + w1 * b01.x;
        o.y = w0 * a01.y + w1 * b01.y;
        o.z = w0 * a23.x + w1 * b23.x;
        o.w = w0 * a23.y + w1 * b23.y;
        out[i] = o;
    }
}

// ---------------------------------------------------------------------------
extern "C" void kernel_launch(void* const* d_in, const int* in_sizes, int n_in,
                              void* d_out, int out_size) {
    const float* X  = (const float*)d_in[0];
    const float* G  = (const float*)d_in[1];
    const float* W1 = (const float*)d_in[2];
    const float* W2 = (const float*)d_in[3];
    float* out = (float*)d_out;

    bool has_logits = (long long)out_size >= (long long)SEQ * HID + (long long)SEQ * NE;
    float* logits = has_logits ? out + (size_t)SEQ * HID : nullptr;

    cudaFuncSetAttribute(gemm1_kernel, cudaFuncAttributeMaxDynamicSharedMemorySize, GSMEM);
    cudaFuncSetAttribute(gemm2_kernel, cudaFuncAttributeMaxDynamicSharedMemorySize, GSMEM);

    reset_kernel<<<1, 32>>>();
    router_kernel<<<SEQ / 8, 256>>>(X, G, logits);
    conv_all_kernel<<<8192, 256>>>((const float4*)X, (const float4*)W1, (const float4*)W2);
    gemm1_kernel<<<dim3(CAP / 128, FFN / 64, NE), 512, GSMEM>>>();
    gemm2_kernel<<<dim3(CAP / 128, HID / 128, NE), 512, GSMEM>>>();
    combine_kernel<<<4096, 256>>>((float4*)out);
}